// round 15
// baseline (speedup 1.0000x reference)
#include <cuda_runtime.h>
#include <cuda_bf16.h>
#include <cstdint>

#define BB 16
#define NNODE 512
#define MNB 16
#define HH 8
#define DD 128
#define BN 8192
#define HD 1024
#define FFD 256

// ---------------- scratch globals ----------------
__device__ float g_Wh[(size_t)BN * HD];
__device__ float g_ssrc[(size_t)BN * HH];
__device__ float g_sdst[(size_t)BN * HH];
__device__ float g_attn[(size_t)BN * 128];          // [node][h*16+m]
__device__ float g_t[(size_t)BN * DD];              // fp32 (LN2 residual)
__device__ float g_part[(size_t)4 * BN * DD];       // split-K partials

// pre-split bf16 hi/lo GEMM inputs (written by producers)
__device__ __nv_bfloat16 g_h_hi[(size_t)BN * DD];
__device__ __nv_bfloat16 g_h_lo[(size_t)BN * DD];
__device__ __nv_bfloat16 g_agg_hi[(size_t)BN * HD];
__device__ __nv_bfloat16 g_agg_lo[(size_t)BN * HD];
__device__ __nv_bfloat16 g_t_hi[(size_t)BN * DD];
__device__ __nv_bfloat16 g_t_lo[(size_t)BN * DD];
__device__ __nv_bfloat16 g_u_hi[(size_t)BN * FFD];
__device__ __nv_bfloat16 g_u_lo[(size_t)BN * FFD];

__device__ __nv_bfloat16 g_Wt_hi[(size_t)HH * DD * DD];  // [h][e][d]
__device__ __nv_bfloat16 g_Wt_lo[(size_t)HH * DD * DD];
__device__ __nv_bfloat16 g_Wot_hi[(size_t)DD * HD];      // [n][k]
__device__ __nv_bfloat16 g_Wot_lo[(size_t)DD * HD];
__device__ __nv_bfloat16 g_w1t_hi[(size_t)FFD * DD];
__device__ __nv_bfloat16 g_w1t_lo[(size_t)FFD * DD];
__device__ __nv_bfloat16 g_w2t_hi[(size_t)DD * FFD];
__device__ __nv_bfloat16 g_w2t_lo[(size_t)DD * FFD];

// ---------------- smem layout (GEMM: M-tile = 64 -> 2 CTAs/SM) ----------------
#define APITCH 136
#define MT 64
#define A_TILE_BYTES (MT * APITCH * 2)      // 17408
#define B_TILE_BYTES (128 * APITCH * 2)     // 34816
#define OFF_AH 2048
#define OFF_AL (OFF_AH + A_TILE_BYTES)
#define OFF_BH (OFF_AL + A_TILE_BYTES)
#define OFF_BL (OFF_BH + B_TILE_BYTES)
#define GEMM_SMEM (OFF_BL + B_TILE_BYTES)   // 106496
#define SPITCH 132

// k2b smem: Wh slice [512][64] fp32 + staged nlist/attn chunk (128 nodes)
#define K2B_WH   131072
#define K2B_NL   (K2B_WH)
#define K2B_AT   (K2B_WH + 8192)
#define K2B_SMEM (K2B_WH + 16384)           // 147456

__device__ __forceinline__ void mma16816(float* d, const uint32_t* a,
                                         uint32_t b0, uint32_t b1) {
    asm volatile(
        "mma.sync.aligned.m16n8k16.row.col.f32.bf16.bf16.f32 "
        "{%0,%1,%2,%3}, {%4,%5,%6,%7}, {%8,%9}, {%0,%1,%2,%3};"
        : "+f"(d[0]), "+f"(d[1]), "+f"(d[2]), "+f"(d[3])
        : "r"(a[0]), "r"(a[1]), "r"(a[2]), "r"(a[3]), "r"(b0), "r"(b1));
}
__device__ __forceinline__ void ldsm_x4(uint32_t* r, uint32_t addr) {
    asm volatile(
        "ldmatrix.sync.aligned.m8n8.x4.shared.b16 {%0,%1,%2,%3}, [%4];"
        : "=r"(r[0]), "=r"(r[1]), "=r"(r[2]), "=r"(r[3]) : "r"(addr));
}
__device__ __forceinline__ void cp_async16(uint32_t saddr, const void* gaddr) {
    asm volatile("cp.async.cg.shared.global [%0], [%1], 16;"
                 :: "r"(saddr), "l"(gaddr));
}
__device__ __forceinline__ void cp_async_wait_all() {
    asm volatile("cp.async.commit_group;");
    asm volatile("cp.async.wait_group 0;");
}
__device__ __forceinline__ void split4(float4 v, uint2& hi, uint2& lo) {
    __nv_bfloat162 h0 = __floats2bfloat162_rn(v.x, v.y);
    __nv_bfloat162 h1 = __floats2bfloat162_rn(v.z, v.w);
    __nv_bfloat162 l0 = __floats2bfloat162_rn(v.x - __bfloat162float(h0.x),
                                              v.y - __bfloat162float(h0.y));
    __nv_bfloat162 l1 = __floats2bfloat162_rn(v.z - __bfloat162float(h1.x),
                                              v.w - __bfloat162float(h1.y));
    hi = make_uint2(*(uint32_t*)&h0, *(uint32_t*)&h1);
    lo = make_uint2(*(uint32_t*)&l0, *(uint32_t*)&l1);
}
__device__ __forceinline__ float warp_sum(float v) {
#pragma unroll
    for (int o = 16; o > 0; o >>= 1) v += __shfl_xor_sync(0xffffffffu, v, o);
    return v;
}

// ---------------- prep: transpose + bf16-split weights AND h ----------------
__global__ void __launch_bounds__(256) prep_weights(
    const float* __restrict__ W, const float* __restrict__ Wo,
    const float* __restrict__ w1, const float* __restrict__ w2,
    const float* __restrict__ hx)
{
    int i = blockIdx.x * 256 + threadIdx.x;
    float v; size_t dst; __nv_bfloat16 *ph, *pl;
    if (i < 131072) {
        int h = i >> 14, d = (i >> 7) & 127, e = i & 127;
        v = W[i]; dst = (size_t)h * 16384 + (size_t)e * 128 + d;
        ph = g_Wt_hi; pl = g_Wt_lo;
    } else if (i < 262144) {
        int j = i - 131072; int k = j >> 7, n = j & 127;
        v = Wo[j]; dst = (size_t)n * 1024 + k;
        ph = g_Wot_hi; pl = g_Wot_lo;
    } else if (i < 294912) {
        int j = i - 262144; int k = j >> 8, n = j & 255;
        v = w1[j]; dst = (size_t)n * 128 + k;
        ph = g_w1t_hi; pl = g_w1t_lo;
    } else if (i < 327680) {
        int j = i - 294912; int k = j >> 7, n = j & 127;
        v = w2[j]; dst = (size_t)n * 256 + k;
        ph = g_w2t_hi; pl = g_w2t_lo;
    } else if (i < 327680 + BN * DD) {
        int j = i - 327680;
        v = hx[j]; dst = j;
        ph = g_h_hi; pl = g_h_lo;
    } else return;
    __nv_bfloat16 hb = __float2bfloat16(v);
    ph[dst] = hb;
    pl[dst] = __float2bfloat16(v - __bfloat162float(hb));
}

// ---------------- HMMA GEMM (unchanged from R14 measured config) ----------------
// MODE 0: Wh = h @ W[head], + ssrc/sdst        grid(128, 8)
// MODE 1: part = agg @ Wo  (split-K 4)         grid(128, 4), raw partials
// MODE 2: u = relu(t @ w1 + b1) -> u hi/lo     grid(128, 2)
// MODE 3: part = u @ w2   (split-K 2)          grid(128, 2), raw partials
template <int MODE>
__global__ void __launch_bounds__(256, 2) gemm_mma(
    const float* __restrict__ p0, const float* __restrict__ p1)
{
    extern __shared__ char sm[];
    const int tid = threadIdx.x;
    const int warp = tid >> 5;
    const int lane = tid & 31;
    const int n0 = blockIdx.x * MT;
    const int by = blockIdx.y;
    const int wm = (warp & 1) * 32;
    const int wn = (warp >> 1) * 32;
    const int rr = lane >> 2;
    const int cc = (lane & 3) * 2;
    const int lrow = lane & 15;
    const int lcol = (lane >> 4) * 8;

    constexpr int LDA = (MODE == 0) ? 128 : (MODE == 1) ? 1024 : (MODE == 2) ? 128 : 256;
    constexpr int LDB = LDA;
    constexpr int KP  = (MODE == 1) ? 2 : 1;
    constexpr bool SPLIT = (MODE == 1 || MODE == 3);
    constexpr int LDOUT = (MODE == 0) ? 1024 : (MODE == 2) ? 256 : 128;

    const int kbase = (MODE == 1) ? by * 256 : (MODE == 3) ? by * 128 : 0;

    const __nv_bfloat16* Ahg = (MODE == 0) ? g_h_hi : (MODE == 1) ? g_agg_hi
                              : (MODE == 2) ? g_t_hi : g_u_hi;
    const __nv_bfloat16* Alg = (MODE == 0) ? g_h_lo : (MODE == 1) ? g_agg_lo
                              : (MODE == 2) ? g_t_lo : g_u_lo;
    const __nv_bfloat16 *Bhg, *Blg;
    int coff = 0;
    if (MODE == 0) { Bhg = g_Wt_hi + (size_t)by * 16384; Blg = g_Wt_lo + (size_t)by * 16384; coff = by * 128; }
    if (MODE == 1) { Bhg = g_Wot_hi; Blg = g_Wot_lo; }
    if (MODE == 2) { Bhg = g_w1t_hi + (size_t)by * 16384; Blg = g_w1t_lo + (size_t)by * 16384; coff = by * 128; }
    if (MODE == 3) { Bhg = g_w2t_hi; Blg = g_w2t_lo; }
    float* outbase = (MODE == 0) ? g_Wh : (g_part + (size_t)by * BN * DD);

    float* s_v0 = (float*)(sm + 64);
    float* s_v1 = (float*)(sm + 576);
    float* sst  = (float*)(sm + OFF_AH);

    const uint32_t smem_u32 = (uint32_t)__cvta_generic_to_shared(sm);
    const uint32_t ah_b = smem_u32 + OFF_AH;
    const uint32_t al_b = smem_u32 + OFF_AL;
    const uint32_t bh_b = smem_u32 + OFF_BH;
    const uint32_t bl_b = smem_u32 + OFF_BL;

    if (tid < 128 && !SPLIT) {
        if (MODE == 0) { s_v0[tid] = p0[by * 128 + tid]; s_v1[tid] = p1[by * 128 + tid]; }
        if (MODE == 2) { s_v0[tid] = p0[by * 128 + tid]; }
    }

    float d[2][4][4];
#pragma unroll
    for (int mi = 0; mi < 2; mi++)
#pragma unroll
        for (int ni = 0; ni < 4; ni++)
#pragma unroll
            for (int j = 0; j < 4; j++) d[mi][ni][j] = 0.f;

    for (int kp = 0; kp < KP; kp++) {
        const int kb0 = kbase + kp * 128;
#pragma unroll
        for (int t = 0; t < 4; t++) {
            int f8 = t * 256 + tid;
            int row = f8 >> 4, g = f8 & 15;
            uint32_t soff = (uint32_t)(row * APITCH + g * 8) * 2;
            const size_t goff = (size_t)(n0 + row) * LDA + kb0 + g * 8;
            cp_async16(ah_b + soff, Ahg + goff);
            cp_async16(al_b + soff, Alg + goff);
        }
#pragma unroll
        for (int t = 0; t < 8; t++) {
            int f8 = t * 256 + tid;
            int n = f8 >> 4, g = f8 & 15;
            uint32_t soff = (uint32_t)(n * APITCH + g * 8) * 2;
            const size_t goff = (size_t)n * LDB + kb0 + g * 8;
            cp_async16(bh_b + soff, Bhg + goff);
            cp_async16(bl_b + soff, Blg + goff);
        }
        cp_async_wait_all();
        __syncthreads();

#pragma unroll
        for (int ks = 0; ks < 8; ks++) {
            const int ck = ks * 16;
            uint32_t ah[2][4], al[2][4], bhf[2][4], blf[2][4];
#pragma unroll
            for (int mi = 0; mi < 2; mi++) {
                uint32_t aoff = (uint32_t)((wm + mi * 16 + lrow) * APITCH + ck + lcol) * 2;
                ldsm_x4(ah[mi], ah_b + aoff);
                ldsm_x4(al[mi], al_b + aoff);
            }
#pragma unroll
            for (int p = 0; p < 2; p++) {
                uint32_t boff = (uint32_t)((wn + p * 16 + lrow) * APITCH + ck + lcol) * 2;
                ldsm_x4(bhf[p], bh_b + boff);
                ldsm_x4(blf[p], bl_b + boff);
            }
#pragma unroll
            for (int mi = 0; mi < 2; mi++)
#pragma unroll
                for (int ni = 0; ni < 4; ni++) {
                    const int p = ni >> 1, o = ni & 1;
                    mma16816(d[mi][ni], ah[mi], bhf[p][o], bhf[p][o + 2]);
                }
#pragma unroll
            for (int mi = 0; mi < 2; mi++)
#pragma unroll
                for (int ni = 0; ni < 4; ni++) {
                    const int p = ni >> 1, o = ni & 1;
                    mma16816(d[mi][ni], ah[mi], blf[p][o], blf[p][o + 2]);
                }
#pragma unroll
            for (int mi = 0; mi < 2; mi++)
#pragma unroll
                for (int ni = 0; ni < 4; ni++) {
                    const int p = ni >> 1, o = ni & 1;
                    mma16816(d[mi][ni], al[mi], bhf[p][o], bhf[p][o + 2]);
                }
        }
        __syncthreads();
    }

    // stage D -> smem
#pragma unroll
    for (int mi = 0; mi < 2; mi++)
#pragma unroll
        for (int ni = 0; ni < 4; ni++) {
            int r = wm + mi * 16 + rr, c = wn + ni * 8 + cc;
            *(float2*)(sst + (size_t)r * SPITCH + c)       = make_float2(d[mi][ni][0], d[mi][ni][1]);
            *(float2*)(sst + (size_t)(r + 8) * SPITCH + c) = make_float2(d[mi][ni][2], d[mi][ni][3]);
        }
    __syncthreads();

    if (tid < MT && !SPLIT) {
        float4* row4 = (float4*)(sst + (size_t)tid * SPITCH);
        const int grow = n0 + tid;
        if (MODE == 0) {
            float ps = 0.f, pd = 0.f;
            const float4* sv0 = (const float4*)s_v0;
            const float4* sv1 = (const float4*)s_v1;
#pragma unroll
            for (int q = 0; q < 32; q++) {
                float4 v = row4[q], a = sv0[q], b = sv1[q];
                ps += v.x * a.x + v.y * a.y + v.z * a.z + v.w * a.w;
                pd += v.x * b.x + v.y * b.y + v.z * b.z + v.w * b.w;
            }
            g_ssrc[(size_t)grow * HH + by] = ps;
            g_sdst[(size_t)grow * HH + by] = pd;
        } else if (MODE == 2) {
            const float4* bv = (const float4*)s_v0;
#pragma unroll
            for (int q = 0; q < 32; q++) {
                float4 v = row4[q], b = bv[q];
                v.x = fmaxf(v.x + b.x, 0.f); v.y = fmaxf(v.y + b.y, 0.f);
                v.z = fmaxf(v.z + b.z, 0.f); v.w = fmaxf(v.w + b.w, 0.f);
                row4[q] = v;
            }
        }
    }
    __syncthreads();

    for (int idx = tid; idx < MT * 32; idx += 256) {
        int rr2 = idx >> 5, q = idx & 31;
        float4 v = *(const float4*)(sst + (size_t)rr2 * SPITCH + q * 4);
        if (MODE == 2) {
            uint2 hi, lo; split4(v, hi, lo);
            size_t o = (size_t)(n0 + rr2) * LDOUT + coff + q * 4;
            *(uint2*)(g_u_hi + o) = hi;
            *(uint2*)(g_u_lo + o) = lo;
        } else {
            *(float4*)(outbase + (size_t)(n0 + rr2) * LDOUT + coff + q * 4) = v;
        }
    }
}

// ---------------- split-K reduce + residual (+bias) + LayerNorm ----------------
// RES_EXT / OUT_EXT select harness pointers vs device globals referenced
// directly in device code. NEVER pass __device__ globals as kernel args from
// host (host shadow address + GB300 ATS = silent writes to host memory).
template <int NP, bool BIAS, bool RES_EXT, bool OUT_EXT>
__global__ void __launch_bounds__(256) ln_reduce(
    const float* __restrict__ res, const float* __restrict__ bias,
    const float* __restrict__ gam, const float* __restrict__ bet,
    float* __restrict__ outp)
{
    const int row = blockIdx.x * 8 + (threadIdx.x >> 5);
    const int lane = threadIdx.x & 31;
    const float* resp = RES_EXT ? (res + (size_t)row * 128) : (g_t + (size_t)row * 128);

    float4 acc = *(const float4*)(resp + lane * 4);
#pragma unroll
    for (int p = 0; p < NP; p++) {
        float4 v = *(const float4*)(g_part + (size_t)p * BN * DD + (size_t)row * 128 + lane * 4);
        acc.x += v.x; acc.y += v.y; acc.z += v.z; acc.w += v.w;
    }
    if (BIAS) {
        float4 b = *(const float4*)(bias + lane * 4);
        acc.x += b.x; acc.y += b.y; acc.z += b.z; acc.w += b.w;
    }
    const float mu = warp_sum(acc.x + acc.y + acc.z + acc.w) * (1.f / 128.f);
    float x0 = acc.x - mu, x1 = acc.y - mu, x2 = acc.z - mu, x3 = acc.w - mu;
    const float var = warp_sum(x0 * x0 + x1 * x1 + x2 * x2 + x3 * x3) * (1.f / 128.f);
    const float rs = rsqrtf(var + 1e-5f);
    float4 g = *(const float4*)(gam + lane * 4);
    float4 b = *(const float4*)(bet + lane * 4);
    float4 y;
    y.x = x0 * rs * g.x + b.x; y.y = x1 * rs * g.y + b.y;
    y.z = x2 * rs * g.z + b.z; y.w = x3 * rs * g.w + b.w;
    if (OUT_EXT) {
        *(float4*)(outp + (size_t)row * 128 + lane * 4) = y;
    } else {
        *(float4*)(g_t + (size_t)row * 128 + lane * 4) = y;
        uint2 hi, lo; split4(y, hi, lo);
        *(uint2*)(g_t_hi + (size_t)row * 128 + lane * 4) = hi;
        *(uint2*)(g_t_lo + (size_t)row * 128 + lane * 4) = lo;
    }
}

// ---------------- K2a: attention weights -> g_attn ----------------
__global__ void __launch_bounds__(256) k2a_weights(
    const int* __restrict__ adj, const int* __restrict__ nlist)
{
    const int node = blockIdx.x * 32 + (threadIdx.x >> 3);
    const int hh = threadIdx.x & 7;
    const int b = node >> 9;
    const float ssrc = g_ssrc[(size_t)node * HH + hh];

    float e[MNB]; float mx = -3.4e38f;
#pragma unroll
    for (int m = 0; m < MNB; m++) {
        int nl = nlist[(size_t)node * MNB + m];
        int av = adj[(size_t)node * MNB + m];
        float v = ssrc + g_sdst[(size_t)((b << 9) + nl) * HH + hh];
        v = v > 0.f ? v : 0.2f * v;
        if (av <= 0) v = -1e9f;
        e[m] = v; mx = fmaxf(mx, v);
    }
    float s = 0.f;
#pragma unroll
    for (int m = 0; m < MNB; m++) { e[m] = expf(e[m] - mx); s += e[m]; }
    const float inv = 1.f / s;
#pragma unroll
    for (int m = 0; m < MNB; m++)
        g_attn[(size_t)node * 128 + hh * MNB + m] = e[m] * inv;
}

// ---------------- K2b: smem-resident aggregation, v2 ----------------
// grid (2 halves, 8 heads, 16 batches); 144KB smem.
// Fix vs R9: nlist/attn staged cooperatively (coalesced) in 128-node chunks,
// eliminating the 64x-redundant uncoalesced scalar global loads.
__global__ void __launch_bounds__(256, 1) k2b_agg(const int* __restrict__ nlist)
{
    extern __shared__ char smraw[];
    float* sWh = (float*)smraw;                    // [512*64]
    int*   snl = (int*)(smraw + K2B_NL);           // [128*16]
    float* sat = (float*)(smraw + K2B_AT);         // [128*16]
    const int half = blockIdx.x, head = blockIdx.y, batch = blockIdx.z;
    const int tid = threadIdx.x;

    // load Wh slice [512 nodes][64 dims] (float4, coalesced)
    const float4* whb = (const float4*)(g_Wh + (size_t)batch * 512 * 1024);
    float4* sWh4 = (float4*)sWh;
#pragma unroll
    for (int t = 0; t < 32; t++) {
        int i = t * 256 + tid;
        int nodel = i >> 4, q = i & 15;
        sWh4[i] = whb[(size_t)nodel * 256 + head * 32 + half * 16 + q];
    }

    const int e = tid & 63;          // dim within half
    const int nsub = tid >> 6;       // 0..3 (32 nodes each per chunk)

    for (int c = 0; c < 4; c++) {
        __syncthreads();             // Wh ready (c=0) / prev chunk consumed
        // stage nlist (contiguous 8KB) + attn (64B rows) for 128 nodes
        const int nbase = (batch << 9) + (c << 7);
        for (int i = tid; i < 128 * 16; i += 256) {
            snl[i] = nlist[(size_t)nbase * 16 + i];
            int nodel = i >> 4, m = i & 15;
            sat[i] = g_attn[(size_t)(nbase + nodel) * 128 + head * 16 + m];
        }
        __syncthreads();

#pragma unroll 4
        for (int j = 0; j < 32; j++) {
            const int nodel = (nsub << 5) + j;
            float acc = 0.f;
#pragma unroll
            for (int m = 0; m < MNB; m++) {
                int nl = snl[nodel * 16 + m];          // broadcast LDS
                float aw = sat[nodel * 16 + m];        // broadcast LDS
                acc = fmaf(aw, sWh[nl * 64 + e], acc); // conflict-free LDS
            }
            const size_t o = (size_t)(nbase + nodel) * 1024 + head * 128 + half * 64 + e;
            __nv_bfloat16 hb = __float2bfloat16(acc);
            g_agg_hi[o] = hb;
            g_agg_lo[o] = __float2bfloat16(acc - __bfloat162float(hb));
        }
    }
}

// ---------------------------------------------------------------------------
extern "C" void kernel_launch(void* const* d_in, const int* in_sizes, int n_in,
                              void* d_out, int out_size)
{
    const float* h     = (const float*)d_in[0];
    const int*   adj   = (const int*)d_in[1];
    const int*   nlist = (const int*)d_in[2];
    const float* W     = (const float*)d_in[3];
    const float* a_src = (const float*)d_in[4];
    const float* a_dst = (const float*)d_in[5];
    const float* Wo    = (const float*)d_in[6];
    const float* ln1g  = (const float*)d_in[7];
    const float* ln1b  = (const float*)d_in[8];
    const float* w1    = (const float*)d_in[9];
    const float* b1    = (const float*)d_in[10];
    const float* w2    = (const float*)d_in[11];
    const float* b2    = (const float*)d_in[12];
    const float* ln2g  = (const float*)d_in[13];
    const float* ln2b  = (const float*)d_in[14];
    float* out = (float*)d_out;

    static bool attr_done = false;
    if (!attr_done) {
        cudaFuncSetAttribute(gemm_mma<0>, cudaFuncAttributeMaxDynamicSharedMemorySize, GEMM_SMEM);
        cudaFuncSetAttribute(gemm_mma<1>, cudaFuncAttributeMaxDynamicSharedMemorySize, GEMM_SMEM);
        cudaFuncSetAttribute(gemm_mma<2>, cudaFuncAttributeMaxDynamicSharedMemorySize, GEMM_SMEM);
        cudaFuncSetAttribute(gemm_mma<3>, cudaFuncAttributeMaxDynamicSharedMemorySize, GEMM_SMEM);
        cudaFuncSetAttribute(k2b_agg, cudaFuncAttributeMaxDynamicSharedMemorySize, K2B_SMEM);
        attr_done = true;
    }

    prep_weights<<<(327680 + BN * DD + 255) / 256, 256>>>(W, Wo, w1, w2, h);
    gemm_mma<0><<<dim3(128, 8), 256, GEMM_SMEM>>>(a_src, a_dst);
    k2a_weights<<<256, 256>>>(adj, nlist);
    k2b_agg<<<dim3(2, 8, 16), 256, K2B_SMEM>>>(nlist);
    gemm_mma<1><<<dim3(128, 4), 256, GEMM_SMEM>>>(nullptr, nullptr);
    // LN1: res = h (ext), out -> g_t + g_t_hi/lo (internal)
    ln_reduce<4, false, true, false><<<1024, 256>>>(h, nullptr, ln1g, ln1b, nullptr);
    gemm_mma<2><<<dim3(128, 2), 256, GEMM_SMEM>>>(b1, nullptr);
    gemm_mma<3><<<dim3(128, 2), 256, GEMM_SMEM>>>(nullptr, nullptr);
    // LN2: res = g_t (internal), out -> d_out (ext)
    ln_reduce<2, true, false, true><<<1024, 256>>>(nullptr, b2, ln2g, ln2b, out);
}

// round 16
// speedup vs baseline: 1.3887x; 1.3887x over previous
#include <cuda_runtime.h>
#include <cuda_bf16.h>
#include <cstdint>

#define BB 16
#define NNODE 512
#define MNB 16
#define HH 8
#define DD 128
#define BN 8192
#define HD 1024
#define FFD 256

// ---------------- scratch globals ----------------
__device__ float g_ssrc[(size_t)BN * HH];
__device__ float g_sdst[(size_t)BN * HH];
__device__ float g_agg[(size_t)BN * HD];            // attn-aggregated raw h, per head
__device__ float g_t[(size_t)BN * DD];
__device__ float g_u[(size_t)BN * FFD];
__device__ float g_part[(size_t)4 * BN * DD];       // split-K partials
__device__ float g_wsrc[(size_t)HH * DD];           // W_h @ a_src_h
__device__ float g_wdst[(size_t)HH * DD];           // W_h @ a_dst_h

// bf16 hi/lo split weights (B operands, [n][k] layouts)
__device__ __nv_bfloat16 g_Wft_hi[(size_t)DD * HD];      // fused (W@Wo)^T: [e2][h*128+d]
__device__ __nv_bfloat16 g_Wft_lo[(size_t)DD * HD];
__device__ __nv_bfloat16 g_w1t_hi[(size_t)FFD * DD];     // [n][k] ldb=128
__device__ __nv_bfloat16 g_w1t_lo[(size_t)FFD * DD];
__device__ __nv_bfloat16 g_w2t_hi[(size_t)DD * FFD];     // [n][k] ldb=256
__device__ __nv_bfloat16 g_w2t_lo[(size_t)DD * FFD];

// ---------------- smem layout (GEMM: M-tile = 64 -> 2 CTAs/SM) ----------------
#define APITCH 136
#define MT 64
#define A_TILE_BYTES (MT * APITCH * 2)
#define B_TILE_BYTES (128 * APITCH * 2)
#define OFF_AH 2048
#define OFF_AL (OFF_AH + A_TILE_BYTES)
#define OFF_BH (OFF_AL + A_TILE_BYTES)
#define OFF_BL (OFF_BH + B_TILE_BYTES)
#define GEMM_SMEM (OFF_BL + B_TILE_BYTES)   // 106496
#define SPITCH 132

__device__ __forceinline__ uint32_t lds32(const __nv_bfloat16* base, int r, int c) {
    return *(const uint32_t*)((const char*)base + ((size_t)r * APITCH + c) * 2);
}
__device__ __forceinline__ void mma16816(float* d, const uint32_t* a,
                                         uint32_t b0, uint32_t b1) {
    asm volatile(
        "mma.sync.aligned.m16n8k16.row.col.f32.bf16.bf16.f32 "
        "{%0,%1,%2,%3}, {%4,%5,%6,%7}, {%8,%9}, {%0,%1,%2,%3};"
        : "+f"(d[0]), "+f"(d[1]), "+f"(d[2]), "+f"(d[3])
        : "r"(a[0]), "r"(a[1]), "r"(a[2]), "r"(a[3]), "r"(b0), "r"(b1));
}
__device__ __forceinline__ void split4(float4 v, uint2& hi, uint2& lo) {
    __nv_bfloat162 h0 = __floats2bfloat162_rn(v.x, v.y);
    __nv_bfloat162 h1 = __floats2bfloat162_rn(v.z, v.w);
    __nv_bfloat162 l0 = __floats2bfloat162_rn(v.x - __bfloat162float(h0.x),
                                              v.y - __bfloat162float(h0.y));
    __nv_bfloat162 l1 = __floats2bfloat162_rn(v.z - __bfloat162float(h1.x),
                                              v.w - __bfloat162float(h1.y));
    hi = make_uint2(*(uint32_t*)&h0, *(uint32_t*)&h1);
    lo = make_uint2(*(uint32_t*)&l0, *(uint32_t*)&l1);
}
__device__ __forceinline__ float warp_sum(float v) {
#pragma unroll
    for (int o = 16; o > 0; o >>= 1) v += __shfl_xor_sync(0xffffffffu, v, o);
    return v;
}

// ---------------- kfuse: Wf = W_h @ Wo_h (split to bf16), wsrc/wdst vectors ----------------
// blocks 0..1023: (h,d) rows of Wf; threads = e2. blocks 1024..1031: wsrc/wdst per head.
__global__ void __launch_bounds__(128) kfuse(
    const float* __restrict__ W, const float* __restrict__ Wo,
    const float* __restrict__ a_src, const float* __restrict__ a_dst)
{
    const int blk = blockIdx.x;
    if (blk < 1024) {
        const int h = blk >> 7, d = blk & 127;
        const int e2 = threadIdx.x;
        const float* wrow = W + ((size_t)h * 128 + d) * 128;   // W[h][d][:]
        float acc = 0.f;
#pragma unroll 4
        for (int e = 0; e < 128; e++)
            acc = fmaf(wrow[e], Wo[((size_t)h * 128 + e) * 128 + e2], acc);
        // store transposed for GEMM B: [n=e2][k=h*128+d]
        const size_t dst = (size_t)e2 * 1024 + h * 128 + d;
        __nv_bfloat16 hb = __float2bfloat16(acc);
        g_Wft_hi[dst] = hb;
        g_Wft_lo[dst] = __float2bfloat16(acc - __bfloat162float(hb));
    } else {
        const int h = blk - 1024;
        const int d = threadIdx.x;
        const float* wrow = W + ((size_t)h * 128 + d) * 128;
        float as = 0.f, ad = 0.f;
#pragma unroll 4
        for (int e = 0; e < 128; e++) {
            float w = wrow[e];
            as = fmaf(w, a_src[h * 128 + e], as);
            ad = fmaf(w, a_dst[h * 128 + e], ad);
        }
        g_wsrc[h * 128 + d] = as;
        g_wdst[h * 128 + d] = ad;
    }
}

// ---------------- prep: transpose + bf16-split FFN weights ----------------
__global__ void __launch_bounds__(256) prep_weights(
    const float* __restrict__ w1, const float* __restrict__ w2)
{
    int i = blockIdx.x * 256 + threadIdx.x;
    float v; size_t dst; __nv_bfloat16 *ph, *pl;
    if (i < 32768) {                        // w1[k][n] -> w1t[n][k]
        int k = i >> 8, n = i & 255;
        v = w1[i]; dst = (size_t)n * 128 + k;
        ph = g_w1t_hi; pl = g_w1t_lo;
    } else if (i < 65536) {                 // w2[k][n] -> w2t[n][k]
        int j = i - 32768; int k = j >> 7, n = j & 127;
        v = w2[j]; dst = (size_t)n * 256 + k;
        ph = g_w2t_hi; pl = g_w2t_lo;
    } else return;
    __nv_bfloat16 hb = __float2bfloat16(v);
    ph[dst] = hb;
    pl[dst] = __float2bfloat16(v - __bfloat162float(hb));
}

// ---------------- ks: s_src/s_dst = h . wsrc/wdst (per node, per head) ----------------
__global__ void __launch_bounds__(256) ks(const float* __restrict__ h)
{
    __shared__ float ws[HH * DD], wd[HH * DD];
    const int tid = threadIdx.x;
    for (int i = tid; i < HH * DD; i += 256) { ws[i] = g_wsrc[i]; wd[i] = g_wdst[i]; }
    __syncthreads();

    const int node = blockIdx.x * 8 + (tid >> 5);
    const int lane = tid & 31;
    const float4 hv = ((const float4*)(h + (size_t)node * 128))[lane];
#pragma unroll
    for (int hh = 0; hh < HH; hh++) {
        float4 a = ((const float4*)ws)[hh * 32 + lane];
        float4 b = ((const float4*)wd)[hh * 32 + lane];
        float ps = hv.x * a.x + hv.y * a.y + hv.z * a.z + hv.w * a.w;
        float pd = hv.x * b.x + hv.y * b.y + hv.z * b.z + hv.w * b.w;
        ps = warp_sum(ps);
        pd = warp_sum(pd);
        if (lane == 0) {
            g_ssrc[(size_t)node * HH + hh] = ps;
            g_sdst[(size_t)node * HH + hh] = pd;
        }
    }
}

// ---------------- K2: softmax + gather-aggregate RAW h (512B/nbr, head-shared) ----------------
__global__ void __launch_bounds__(256) k2_attn(
    const int* __restrict__ adj, const int* __restrict__ nlist,
    const float* __restrict__ h)
{
    const int node = blockIdx.x;
    const int b = node >> 9;
    const int tx = threadIdx.x;

    __shared__ int   nls[MNB];
    __shared__ int   adjs[MNB];
    __shared__ float es[MNB][HH];
    __shared__ float attn_s[MNB][HH];

    if (tx < MNB) {
        nls[tx]  = nlist[(size_t)node * MNB + tx];
        adjs[tx] = adj[(size_t)node * MNB + tx];
    }
    __syncthreads();

    if (tx < MNB * HH) {
        const int m = tx >> 3, hh = tx & 7;
        float v = g_ssrc[(size_t)node * HH + hh]
                + g_sdst[(size_t)((b << 9) + nls[m]) * HH + hh];
        v = v > 0.f ? v : 0.2f * v;
        if (adjs[m] <= 0) v = -1e9f;
        es[m][hh] = v;
    }
    __syncthreads();

    if (tx < HH) {
        float mx = -3.4e38f;
#pragma unroll
        for (int m = 0; m < MNB; m++) mx = fmaxf(mx, es[m][tx]);
        float ex[MNB], s = 0.f;
#pragma unroll
        for (int m = 0; m < MNB; m++) { ex[m] = expf(es[m][tx] - mx); s += ex[m]; }
        const float inv = 1.f / s;
#pragma unroll
        for (int m = 0; m < MNB; m++) attn_s[m][tx] = ex[m] * inv;
    }
    __syncthreads();

    // tx = hh*32 + lane; all 8 head-groups read the SAME h float4 (L1 broadcast)
    const int hh = tx >> 5;
    const int lane = tx & 31;
    const float4* hb4 = (const float4*)h + (size_t)(b << 9) * 32;
    float4 acc = make_float4(0.f, 0.f, 0.f, 0.f);
#pragma unroll
    for (int m = 0; m < MNB; m++) {
        const float wgt = attn_s[m][hh];
        const float4 v = hb4[(size_t)nls[m] * 32 + lane];
        acc.x = fmaf(wgt, v.x, acc.x);
        acc.y = fmaf(wgt, v.y, acc.y);
        acc.z = fmaf(wgt, v.z, acc.z);
        acc.w = fmaf(wgt, v.w, acc.w);
    }
    ((float4*)g_agg)[(size_t)node * 256 + tx] = acc;
}

// ---------------- HMMA GEMM (R11-proven core: fp32 A, in-kernel split, lds32) ----------------
// MODE 1: part = agg @ Wf  (split-K 4)         grid(128, 4), raw partials
// MODE 2: u = relu(t @ w1 + b1)                grid(128, 2)
// MODE 3: part = u @ w2   (split-K 2)          grid(128, 2), raw partials
template <int MODE>
__global__ void __launch_bounds__(256, 2) gemm_mma(
    const float* __restrict__ p0, const float* __restrict__ p1)
{
    extern __shared__ char sm[];
    const int tid = threadIdx.x;
    const int warp = tid >> 5;
    const int lane = tid & 31;
    const int n0 = blockIdx.x * MT;
    const int by = blockIdx.y;
    const int wm = (warp & 1) * 32;
    const int wn = (warp >> 1) * 32;
    const int rr = lane >> 2;
    const int cc = (lane & 3) * 2;

    constexpr int LDA = (MODE == 1) ? 1024 : (MODE == 2) ? 128 : 256;
    constexpr int LDB = LDA;
    constexpr int KP  = (MODE == 1) ? 2 : 1;
    constexpr bool SPLIT = (MODE == 1 || MODE == 3);
    constexpr int LDOUT = (MODE == 2) ? 256 : 128;

    const int kbase = (MODE == 1) ? by * 256 : (MODE == 3) ? by * 128 : 0;

    const float* A = (MODE == 1) ? g_agg : (MODE == 2) ? g_t : g_u;
    const __nv_bfloat16 *Bh, *Bl;
    int coff = 0;
    if (MODE == 1) { Bh = g_Wft_hi; Bl = g_Wft_lo; }
    if (MODE == 2) { Bh = g_w1t_hi + (size_t)by * 16384; Bl = g_w1t_lo + (size_t)by * 16384; coff = by * 128; }
    if (MODE == 3) { Bh = g_w2t_hi; Bl = g_w2t_lo; }
    float* outbase = (MODE == 2) ? g_u : (g_part + (size_t)by * BN * DD);

    __nv_bfloat16* Ah_s = (__nv_bfloat16*)(sm + OFF_AH);
    __nv_bfloat16* Al_s = (__nv_bfloat16*)(sm + OFF_AL);
    __nv_bfloat16* Bh_s = (__nv_bfloat16*)(sm + OFF_BH);
    __nv_bfloat16* Bl_s = (__nv_bfloat16*)(sm + OFF_BL);
    float* s_v0 = (float*)(sm + 64);
    float* sst  = (float*)(sm + OFF_AH);

    if (tid < 128 && MODE == 2) s_v0[tid] = p0[by * 128 + tid];

    float d[2][4][4];
#pragma unroll
    for (int mi = 0; mi < 2; mi++)
#pragma unroll
        for (int ni = 0; ni < 4; ni++)
#pragma unroll
            for (int j = 0; j < 4; j++) d[mi][ni][j] = 0.f;

    for (int kp = 0; kp < KP; kp++) {
        const int kb0 = kbase + kp * 128;
        // A tile: 64x128 fp32 -> bf16 hi/lo
#pragma unroll
        for (int t = 0; t < 8; t++) {
            int f4 = t * 256 + tid;
            int row = f4 >> 5, q = f4 & 31;
            float4 v = *(const float4*)(A + (size_t)(n0 + row) * LDA + kb0 + q * 4);
            uint2 hi, lo; split4(v, hi, lo);
            size_t off = ((size_t)row * APITCH + q * 4) * 2;
            *(uint2*)((char*)Ah_s + off) = hi;
            *(uint2*)((char*)Al_s + off) = lo;
        }
        // B tile: 128x128 bf16 hi/lo pre-split
#pragma unroll
        for (int t = 0; t < 8; t++) {
            int f8 = t * 256 + tid;
            int n = f8 >> 4, g = f8 & 15;
            uint4 vh = *(const uint4*)(Bh + (size_t)n * LDB + kb0 + g * 8);
            uint4 vl = *(const uint4*)(Bl + (size_t)n * LDB + kb0 + g * 8);
            size_t off = ((size_t)n * APITCH + g * 8) * 2;
            *(uint4*)((char*)Bh_s + off) = vh;
            *(uint4*)((char*)Bl_s + off) = vl;
        }
        __syncthreads();

#pragma unroll
        for (int ks2 = 0; ks2 < 8; ks2++) {
            const int ck = ks2 * 16;
            uint32_t ah[2][4], al[2][4], bh2[4][2], bl2[4][2];
#pragma unroll
            for (int mi = 0; mi < 2; mi++) {
                int r0 = wm + mi * 16 + rr, c0 = ck + cc;
                ah[mi][0] = lds32(Ah_s, r0, c0);     ah[mi][1] = lds32(Ah_s, r0 + 8, c0);
                ah[mi][2] = lds32(Ah_s, r0, c0 + 8); ah[mi][3] = lds32(Ah_s, r0 + 8, c0 + 8);
                al[mi][0] = lds32(Al_s, r0, c0);     al[mi][1] = lds32(Al_s, r0 + 8, c0);
                al[mi][2] = lds32(Al_s, r0, c0 + 8); al[mi][3] = lds32(Al_s, r0 + 8, c0 + 8);
            }
#pragma unroll
            for (int ni = 0; ni < 4; ni++) {
                int nb = wn + ni * 8 + rr, k0 = ck + cc;
                bh2[ni][0] = lds32(Bh_s, nb, k0); bh2[ni][1] = lds32(Bh_s, nb, k0 + 8);
                bl2[ni][0] = lds32(Bl_s, nb, k0); bl2[ni][1] = lds32(Bl_s, nb, k0 + 8);
            }
#pragma unroll
            for (int mi = 0; mi < 2; mi++)
#pragma unroll
                for (int ni = 0; ni < 4; ni++) {
                    mma16816(d[mi][ni], ah[mi], bh2[ni][0], bh2[ni][1]);
                    mma16816(d[mi][ni], ah[mi], bl2[ni][0], bl2[ni][1]);
                    mma16816(d[mi][ni], al[mi], bh2[ni][0], bh2[ni][1]);
                }
        }
        __syncthreads();
    }

    // stage D -> smem
#pragma unroll
    for (int mi = 0; mi < 2; mi++)
#pragma unroll
        for (int ni = 0; ni < 4; ni++) {
            int r = wm + mi * 16 + rr, c = wn + ni * 8 + cc;
            *(float2*)(sst + (size_t)r * SPITCH + c)       = make_float2(d[mi][ni][0], d[mi][ni][1]);
            *(float2*)(sst + (size_t)(r + 8) * SPITCH + c) = make_float2(d[mi][ni][2], d[mi][ni][3]);
        }
    __syncthreads();

    if (tid < MT && MODE == 2) {
        float4* row4 = (float4*)(sst + (size_t)tid * SPITCH);
        const float4* bv = (const float4*)s_v0;
#pragma unroll
        for (int q = 0; q < 32; q++) {
            float4 v = row4[q], b = bv[q];
            v.x = fmaxf(v.x + b.x, 0.f); v.y = fmaxf(v.y + b.y, 0.f);
            v.z = fmaxf(v.z + b.z, 0.f); v.w = fmaxf(v.w + b.w, 0.f);
            row4[q] = v;
        }
    }
    __syncthreads();

    for (int idx = tid; idx < MT * 32; idx += 256) {
        int rr2 = idx >> 5, q = idx & 31;
        float4 v = *(const float4*)(sst + (size_t)rr2 * SPITCH + q * 4);
        *(float4*)(outbase + (size_t)(n0 + rr2) * LDOUT + coff + q * 4) = v;
    }
}

// ---------------- split-K reduce + residual (+bias) + LayerNorm ----------------
// RES_EXT / OUT_EXT select harness pointers vs device globals referenced
// directly in device code. NEVER pass __device__ globals as kernel args from
// host (host shadow address + GB300 ATS = silent writes to host memory).
template <int NP, bool BIAS, bool RES_EXT, bool OUT_EXT>
__global__ void __launch_bounds__(256) ln_reduce(
    const float* __restrict__ res, const float* __restrict__ bias,
    const float* __restrict__ gam, const float* __restrict__ bet,
    float* __restrict__ outp)
{
    const int row = blockIdx.x * 8 + (threadIdx.x >> 5);
    const int lane = threadIdx.x & 31;
    const float* resp = RES_EXT ? (res + (size_t)row * 128) : (g_t + (size_t)row * 128);
    float* outrow = OUT_EXT ? (outp + (size_t)row * 128 + lane * 4)
                            : (g_t + (size_t)row * 128 + lane * 4);

    float4 acc = *(const float4*)(resp + lane * 4);
#pragma unroll
    for (int p = 0; p < NP; p++) {
        float4 v = *(const float4*)(g_part + (size_t)p * BN * DD + (size_t)row * 128 + lane * 4);
        acc.x += v.x; acc.y += v.y; acc.z += v.z; acc.w += v.w;
    }
    if (BIAS) {
        float4 b = *(const float4*)(bias + lane * 4);
        acc.x += b.x; acc.y += b.y; acc.z += b.z; acc.w += b.w;
    }
    const float mu = warp_sum(acc.x + acc.y + acc.z + acc.w) * (1.f / 128.f);
    float x0 = acc.x - mu, x1 = acc.y - mu, x2 = acc.z - mu, x3 = acc.w - mu;
    const float var = warp_sum(x0 * x0 + x1 * x1 + x2 * x2 + x3 * x3) * (1.f / 128.f);
    const float rs = rsqrtf(var + 1e-5f);
    float4 g = *(const float4*)(gam + lane * 4);
    float4 b = *(const float4*)(bet + lane * 4);
    float4 y;
    y.x = x0 * rs * g.x + b.x; y.y = x1 * rs * g.y + b.y;
    y.z = x2 * rs * g.z + b.z; y.w = x3 * rs * g.w + b.w;
    *(float4*)outrow = y;
}

// ---------------------------------------------------------------------------
extern "C" void kernel_launch(void* const* d_in, const int* in_sizes, int n_in,
                              void* d_out, int out_size)
{
    const float* h     = (const float*)d_in[0];
    const int*   adj   = (const int*)d_in[1];
    const int*   nlist = (const int*)d_in[2];
    const float* W     = (const float*)d_in[3];
    const float* a_src = (const float*)d_in[4];
    const float* a_dst = (const float*)d_in[5];
    const float* Wo    = (const float*)d_in[6];
    const float* ln1g  = (const float*)d_in[7];
    const float* ln1b  = (const float*)d_in[8];
    const float* w1    = (const float*)d_in[9];
    const float* b1    = (const float*)d_in[10];
    const float* w2    = (const float*)d_in[11];
    const float* b2    = (const float*)d_in[12];
    const float* ln2g  = (const float*)d_in[13];
    const float* ln2b  = (const float*)d_in[14];
    float* out = (float*)d_out;

    static bool attr_done = false;
    if (!attr_done) {
        cudaFuncSetAttribute(gemm_mma<1>, cudaFuncAttributeMaxDynamicSharedMemorySize, GEMM_SMEM);
        cudaFuncSetAttribute(gemm_mma<2>, cudaFuncAttributeMaxDynamicSharedMemorySize, GEMM_SMEM);
        cudaFuncSetAttribute(gemm_mma<3>, cudaFuncAttributeMaxDynamicSharedMemorySize, GEMM_SMEM);
        attr_done = true;
    }

    kfuse<<<1032, 128>>>(W, Wo, a_src, a_dst);
    prep_weights<<<256, 256>>>(w1, w2);
    ks<<<BN / 8, 256>>>(h);
    k2_attn<<<BN, 256>>>(adj, nlist, h);
    gemm_mma<1><<<dim3(128, 4), 256, GEMM_SMEM>>>(nullptr, nullptr);
    // LN1: res = h (ext), out -> g_t (internal)
    ln_reduce<4, false, true, false><<<1024, 256>>>(h, nullptr, ln1g, ln1b, nullptr);
    gemm_mma<2><<<dim3(128, 2), 256, GEMM_SMEM>>>(b1, nullptr);
    gemm_mma<3><<<dim3(128, 2), 256, GEMM_SMEM>>>(nullptr, nullptr);
    // LN2: res = g_t (internal), out -> d_out (ext)
    ln_reduce<2, true, false, true><<<1024, 256>>>(nullptr, b2, ln2g, ln2b, out);
}

// round 17
// speedup vs baseline: 1.5838x; 1.1405x over previous
#include <cuda_runtime.h>
#include <cuda_bf16.h>
#include <cstdint>

#define BB 16
#define NNODE 512
#define MNB 16
#define HH 8
#define DD 128
#define BN 8192
#define HD 1024
#define FFD 256

// ---------------- scratch globals ----------------
__device__ float g_ssrc[(size_t)BN * HH];
__device__ float g_sdst[(size_t)BN * HH];
__device__ float g_agg[(size_t)BN * HD];            // attn-aggregated raw h, per head
__device__ float g_t[(size_t)BN * DD];
__device__ float g_u[(size_t)BN * FFD];
__device__ float g_part[(size_t)4 * BN * DD];       // split-K partials
__device__ float g_wsrc[(size_t)HH * DD];           // W_h @ a_src_h
__device__ float g_wdst[(size_t)HH * DD];           // W_h @ a_dst_h

// bf16 hi/lo split weights (B operands, [n][k] layouts)
__device__ __nv_bfloat16 g_Wft_hi[(size_t)DD * HD];      // fused (W@Wo)^T: [e2][h*128+d]
__device__ __nv_bfloat16 g_Wft_lo[(size_t)DD * HD];
__device__ __nv_bfloat16 g_w1t_hi[(size_t)FFD * DD];     // [n][k] ldb=128
__device__ __nv_bfloat16 g_w1t_lo[(size_t)FFD * DD];
__device__ __nv_bfloat16 g_w2t_hi[(size_t)DD * FFD];     // [n][k] ldb=256
__device__ __nv_bfloat16 g_w2t_lo[(size_t)DD * FFD];

// ---------------- smem layout (GEMM: M-tile = 64 -> 2 CTAs/SM) ----------------
#define APITCH 136
#define MT 64
#define A_TILE_BYTES (MT * APITCH * 2)
#define B_TILE_BYTES (128 * APITCH * 2)
#define OFF_AH 2048
#define OFF_AL (OFF_AH + A_TILE_BYTES)
#define OFF_BH (OFF_AL + A_TILE_BYTES)
#define OFF_BL (OFF_BH + B_TILE_BYTES)
#define GEMM_SMEM (OFF_BL + B_TILE_BYTES)   // 106496
#define SPITCH 132

__device__ __forceinline__ uint32_t lds32(const __nv_bfloat16* base, int r, int c) {
    return *(const uint32_t*)((const char*)base + ((size_t)r * APITCH + c) * 2);
}
__device__ __forceinline__ void mma16816(float* d, const uint32_t* a,
                                         uint32_t b0, uint32_t b1) {
    asm volatile(
        "mma.sync.aligned.m16n8k16.row.col.f32.bf16.bf16.f32 "
        "{%0,%1,%2,%3}, {%4,%5,%6,%7}, {%8,%9}, {%0,%1,%2,%3};"
        : "+f"(d[0]), "+f"(d[1]), "+f"(d[2]), "+f"(d[3])
        : "r"(a[0]), "r"(a[1]), "r"(a[2]), "r"(a[3]), "r"(b0), "r"(b1));
}
__device__ __forceinline__ void split4(float4 v, uint2& hi, uint2& lo) {
    __nv_bfloat162 h0 = __floats2bfloat162_rn(v.x, v.y);
    __nv_bfloat162 h1 = __floats2bfloat162_rn(v.z, v.w);
    __nv_bfloat162 l0 = __floats2bfloat162_rn(v.x - __bfloat162float(h0.x),
                                              v.y - __bfloat162float(h0.y));
    __nv_bfloat162 l1 = __floats2bfloat162_rn(v.z - __bfloat162float(h1.x),
                                              v.w - __bfloat162float(h1.y));
    hi = make_uint2(*(uint32_t*)&h0, *(uint32_t*)&h1);
    lo = make_uint2(*(uint32_t*)&l0, *(uint32_t*)&l1);
}
__device__ __forceinline__ float warp_sum(float v) {
#pragma unroll
    for (int o = 16; o > 0; o >>= 1) v += __shfl_xor_sync(0xffffffffu, v, o);
    return v;
}

// ---------------- kfuse: Wf = W_h @ Wo_h (split to bf16), wsrc/wdst vectors ----------------
__global__ void __launch_bounds__(128) kfuse(
    const float* __restrict__ W, const float* __restrict__ Wo,
    const float* __restrict__ a_src, const float* __restrict__ a_dst)
{
    const int blk = blockIdx.x;
    if (blk < 1024) {
        const int h = blk >> 7, d = blk & 127;
        const int e2 = threadIdx.x;
        const float* wrow = W + ((size_t)h * 128 + d) * 128;
        float acc = 0.f;
#pragma unroll 4
        for (int e = 0; e < 128; e++)
            acc = fmaf(wrow[e], Wo[((size_t)h * 128 + e) * 128 + e2], acc);
        const size_t dst = (size_t)e2 * 1024 + h * 128 + d;
        __nv_bfloat16 hb = __float2bfloat16(acc);
        g_Wft_hi[dst] = hb;
        g_Wft_lo[dst] = __float2bfloat16(acc - __bfloat162float(hb));
    } else {
        const int h = blk - 1024;
        const int d = threadIdx.x;
        const float* wrow = W + ((size_t)h * 128 + d) * 128;
        float as = 0.f, ad = 0.f;
#pragma unroll 4
        for (int e = 0; e < 128; e++) {
            float w = wrow[e];
            as = fmaf(w, a_src[h * 128 + e], as);
            ad = fmaf(w, a_dst[h * 128 + e], ad);
        }
        g_wsrc[h * 128 + d] = as;
        g_wdst[h * 128 + d] = ad;
    }
}

// ---------------- prep: transpose + bf16-split FFN weights ----------------
__global__ void __launch_bounds__(256) prep_weights(
    const float* __restrict__ w1, const float* __restrict__ w2)
{
    int i = blockIdx.x * 256 + threadIdx.x;
    float v; size_t dst; __nv_bfloat16 *ph, *pl;
    if (i < 32768) {
        int k = i >> 8, n = i & 255;
        v = w1[i]; dst = (size_t)n * 128 + k;
        ph = g_w1t_hi; pl = g_w1t_lo;
    } else if (i < 65536) {
        int j = i - 32768; int k = j >> 7, n = j & 127;
        v = w2[j]; dst = (size_t)n * 256 + k;
        ph = g_w2t_hi; pl = g_w2t_lo;
    } else return;
    __nv_bfloat16 hb = __float2bfloat16(v);
    ph[dst] = hb;
    pl[dst] = __float2bfloat16(v - __bfloat162float(hb));
}

// ---------------- ks: s_src/s_dst = h . wsrc/wdst ----------------
__global__ void __launch_bounds__(256) ks(const float* __restrict__ h)
{
    __shared__ float ws[HH * DD], wd[HH * DD];
    const int tid = threadIdx.x;
    for (int i = tid; i < HH * DD; i += 256) { ws[i] = g_wsrc[i]; wd[i] = g_wdst[i]; }
    __syncthreads();

    const int node = blockIdx.x * 8 + (tid >> 5);
    const int lane = tid & 31;
    const float4 hv = ((const float4*)(h + (size_t)node * 128))[lane];
#pragma unroll
    for (int hh = 0; hh < HH; hh++) {
        float4 a = ((const float4*)ws)[hh * 32 + lane];
        float4 b = ((const float4*)wd)[hh * 32 + lane];
        float ps = hv.x * a.x + hv.y * a.y + hv.z * a.z + hv.w * a.w;
        float pd = hv.x * b.x + hv.y * b.y + hv.z * b.z + hv.w * b.w;
        ps = warp_sum(ps);
        pd = warp_sum(pd);
        if (lane == 0) {
            g_ssrc[(size_t)node * HH + hh] = ps;
            g_sdst[(size_t)node * HH + hh] = pd;
        }
    }
}

// ---------------- K2: warp-per-node softmax + aggregation (all 8 heads per load) ----------------
// lane = (m = lane>>1, h-quad = (lane&1)*4) for softmax; lane = e-chunk for aggregation.
__global__ void __launch_bounds__(256) k2_attn(
    const int* __restrict__ adj, const int* __restrict__ nlist,
    const float* __restrict__ h)
{
    const int tid = threadIdx.x;
    const int warp = tid >> 5, lane = tid & 31;
    const int node = blockIdx.x * 8 + warp;
    const int b = node >> 9;

    __shared__ int   nls_s[8][MNB];
    __shared__ float attn_s[8][MNB * HH];   // [m*8 + h]

    if (lane < MNB)
        nls_s[warp][lane] = nlist[(size_t)node * MNB + lane];
    __syncwarp();

    // each lane: one m (= lane>>1), four heads (hp..hp+3 where hp = (lane&1)*4)
    const int m = lane >> 1;
    const int hp = (lane & 1) * 4;
    const int nl = nls_s[warp][m];
    const int av = adj[(size_t)node * MNB + m];

    float4 sv = *(const float4*)(g_ssrc + (size_t)node * HH + hp);
    float4 dv = *(const float4*)(g_sdst + ((size_t)((b << 9) + nl)) * HH + hp);
    float e[4] = {sv.x + dv.x, sv.y + dv.y, sv.z + dv.z, sv.w + dv.w};
#pragma unroll
    for (int j = 0; j < 4; j++) {
        e[j] = e[j] > 0.f ? e[j] : 0.2f * e[j];
        if (av <= 0) e[j] = -1e9f;
    }
    // max over the 16 same-parity lanes (all m, fixed h)
    float mx[4] = {e[0], e[1], e[2], e[3]};
#pragma unroll
    for (int off = 2; off <= 16; off <<= 1)
#pragma unroll
        for (int j = 0; j < 4; j++)
            mx[j] = fmaxf(mx[j], __shfl_xor_sync(0xffffffffu, mx[j], off));
    float ex[4], s[4];
#pragma unroll
    for (int j = 0; j < 4; j++) { ex[j] = expf(e[j] - mx[j]); s[j] = ex[j]; }
#pragma unroll
    for (int off = 2; off <= 16; off <<= 1)
#pragma unroll
        for (int j = 0; j < 4; j++)
            s[j] += __shfl_xor_sync(0xffffffffu, s[j], off);
    float4 at;
    at.x = ex[0] / s[0]; at.y = ex[1] / s[1];
    at.z = ex[2] / s[2]; at.w = ex[3] / s[3];
    *(float4*)&attn_s[warp][m * 8 + hp] = at;   // = linear index lane*4
    __syncwarp();

    // aggregation: lane = e-chunk (float4); one load serves all 8 heads
    const float4* hb4 = (const float4*)h + (size_t)(b << 9) * 32;
    float4 acc[8];
#pragma unroll
    for (int hh = 0; hh < 8; hh++) acc[hh] = make_float4(0.f, 0.f, 0.f, 0.f);
#pragma unroll
    for (int m2 = 0; m2 < MNB; m2++) {
        const int nn = nls_s[warp][m2];
        const float4 hv = hb4[(size_t)nn * 32 + lane];
        const float4 w0 = *(const float4*)&attn_s[warp][m2 * 8];      // h 0..3
        const float4 w1 = *(const float4*)&attn_s[warp][m2 * 8 + 4];  // h 4..7
        acc[0].x = fmaf(w0.x, hv.x, acc[0].x); acc[0].y = fmaf(w0.x, hv.y, acc[0].y);
        acc[0].z = fmaf(w0.x, hv.z, acc[0].z); acc[0].w = fmaf(w0.x, hv.w, acc[0].w);
        acc[1].x = fmaf(w0.y, hv.x, acc[1].x); acc[1].y = fmaf(w0.y, hv.y, acc[1].y);
        acc[1].z = fmaf(w0.y, hv.z, acc[1].z); acc[1].w = fmaf(w0.y, hv.w, acc[1].w);
        acc[2].x = fmaf(w0.z, hv.x, acc[2].x); acc[2].y = fmaf(w0.z, hv.y, acc[2].y);
        acc[2].z = fmaf(w0.z, hv.z, acc[2].z); acc[2].w = fmaf(w0.z, hv.w, acc[2].w);
        acc[3].x = fmaf(w0.w, hv.x, acc[3].x); acc[3].y = fmaf(w0.w, hv.y, acc[3].y);
        acc[3].z = fmaf(w0.w, hv.z, acc[3].z); acc[3].w = fmaf(w0.w, hv.w, acc[3].w);
        acc[4].x = fmaf(w1.x, hv.x, acc[4].x); acc[4].y = fmaf(w1.x, hv.y, acc[4].y);
        acc[4].z = fmaf(w1.x, hv.z, acc[4].z); acc[4].w = fmaf(w1.x, hv.w, acc[4].w);
        acc[5].x = fmaf(w1.y, hv.x, acc[5].x); acc[5].y = fmaf(w1.y, hv.y, acc[5].y);
        acc[5].z = fmaf(w1.y, hv.z, acc[5].z); acc[5].w = fmaf(w1.y, hv.w, acc[5].w);
        acc[6].x = fmaf(w1.z, hv.x, acc[6].x); acc[6].y = fmaf(w1.z, hv.y, acc[6].y);
        acc[6].z = fmaf(w1.z, hv.z, acc[6].z); acc[6].w = fmaf(w1.z, hv.w, acc[6].w);
        acc[7].x = fmaf(w1.w, hv.x, acc[7].x); acc[7].y = fmaf(w1.w, hv.y, acc[7].y);
        acc[7].z = fmaf(w1.w, hv.z, acc[7].z); acc[7].w = fmaf(w1.w, hv.w, acc[7].w);
    }
#pragma unroll
    for (int hh = 0; hh < 8; hh++)
        ((float4*)(g_agg + (size_t)node * HD + hh * 128))[lane] = acc[hh];
}

// ---------------- HMMA GEMM (R11-proven core: fp32 A, in-kernel split, lds32) ----------------
// MODE 1: part = agg @ Wf  (split-K 4)         grid(128, 4), raw partials
// MODE 2: u = relu(t @ w1 + b1)                grid(128, 2)
// MODE 3: part = u @ w2   (split-K 2)          grid(128, 2), raw partials
template <int MODE>
__global__ void __launch_bounds__(256, 2) gemm_mma(
    const float* __restrict__ p0, const float* __restrict__ p1)
{
    extern __shared__ char sm[];
    const int tid = threadIdx.x;
    const int warp = tid >> 5;
    const int lane = tid & 31;
    const int n0 = blockIdx.x * MT;
    const int by = blockIdx.y;
    const int wm = (warp & 1) * 32;
    const int wn = (warp >> 1) * 32;
    const int rr = lane >> 2;
    const int cc = (lane & 3) * 2;

    constexpr int LDA = (MODE == 1) ? 1024 : (MODE == 2) ? 128 : 256;
    constexpr int LDB = LDA;
    constexpr int KP  = (MODE == 1) ? 2 : 1;
    constexpr int LDOUT = (MODE == 2) ? 256 : 128;

    const int kbase = (MODE == 1) ? by * 256 : (MODE == 3) ? by * 128 : 0;

    const float* A = (MODE == 1) ? g_agg : (MODE == 2) ? g_t : g_u;
    const __nv_bfloat16 *Bh, *Bl;
    int coff = 0;
    if (MODE == 1) { Bh = g_Wft_hi; Bl = g_Wft_lo; }
    if (MODE == 2) { Bh = g_w1t_hi + (size_t)by * 16384; Bl = g_w1t_lo + (size_t)by * 16384; coff = by * 128; }
    if (MODE == 3) { Bh = g_w2t_hi; Bl = g_w2t_lo; }
    float* outbase = (MODE == 2) ? g_u : (g_part + (size_t)by * BN * DD);

    __nv_bfloat16* Ah_s = (__nv_bfloat16*)(sm + OFF_AH);
    __nv_bfloat16* Al_s = (__nv_bfloat16*)(sm + OFF_AL);
    __nv_bfloat16* Bh_s = (__nv_bfloat16*)(sm + OFF_BH);
    __nv_bfloat16* Bl_s = (__nv_bfloat16*)(sm + OFF_BL);
    float* s_v0 = (float*)(sm + 64);
    float* sst  = (float*)(sm + OFF_AH);

    if (tid < 128 && MODE == 2) s_v0[tid] = p0[by * 128 + tid];

    float d[2][4][4];
#pragma unroll
    for (int mi = 0; mi < 2; mi++)
#pragma unroll
        for (int ni = 0; ni < 4; ni++)
#pragma unroll
            for (int j = 0; j < 4; j++) d[mi][ni][j] = 0.f;

    for (int kp = 0; kp < KP; kp++) {
        const int kb0 = kbase + kp * 128;
#pragma unroll
        for (int t = 0; t < 8; t++) {
            int f4 = t * 256 + tid;
            int row = f4 >> 5, q = f4 & 31;
            float4 v = *(const float4*)(A + (size_t)(n0 + row) * LDA + kb0 + q * 4);
            uint2 hi, lo; split4(v, hi, lo);
            size_t off = ((size_t)row * APITCH + q * 4) * 2;
            *(uint2*)((char*)Ah_s + off) = hi;
            *(uint2*)((char*)Al_s + off) = lo;
        }
#pragma unroll
        for (int t = 0; t < 8; t++) {
            int f8 = t * 256 + tid;
            int n = f8 >> 4, g = f8 & 15;
            uint4 vh = *(const uint4*)(Bh + (size_t)n * LDB + kb0 + g * 8);
            uint4 vl = *(const uint4*)(Bl + (size_t)n * LDB + kb0 + g * 8);
            size_t off = ((size_t)n * APITCH + g * 8) * 2;
            *(uint4*)((char*)Bh_s + off) = vh;
            *(uint4*)((char*)Bl_s + off) = vl;
        }
        __syncthreads();

#pragma unroll
        for (int ks2 = 0; ks2 < 8; ks2++) {
            const int ck = ks2 * 16;
            uint32_t ah[2][4], al[2][4], bh2[4][2], bl2[4][2];
#pragma unroll
            for (int mi = 0; mi < 2; mi++) {
                int r0 = wm + mi * 16 + rr, c0 = ck + cc;
                ah[mi][0] = lds32(Ah_s, r0, c0);     ah[mi][1] = lds32(Ah_s, r0 + 8, c0);
                ah[mi][2] = lds32(Ah_s, r0, c0 + 8); ah[mi][3] = lds32(Ah_s, r0 + 8, c0 + 8);
                al[mi][0] = lds32(Al_s, r0, c0);     al[mi][1] = lds32(Al_s, r0 + 8, c0);
                al[mi][2] = lds32(Al_s, r0, c0 + 8); al[mi][3] = lds32(Al_s, r0 + 8, c0 + 8);
            }
#pragma unroll
            for (int ni = 0; ni < 4; ni++) {
                int nb = wn + ni * 8 + rr, k0 = ck + cc;
                bh2[ni][0] = lds32(Bh_s, nb, k0); bh2[ni][1] = lds32(Bh_s, nb, k0 + 8);
                bl2[ni][0] = lds32(Bl_s, nb, k0); bl2[ni][1] = lds32(Bl_s, nb, k0 + 8);
            }
#pragma unroll
            for (int mi = 0; mi < 2; mi++)
#pragma unroll
                for (int ni = 0; ni < 4; ni++) {
                    mma16816(d[mi][ni], ah[mi], bh2[ni][0], bh2[ni][1]);
                    mma16816(d[mi][ni], ah[mi], bl2[ni][0], bl2[ni][1]);
                    mma16816(d[mi][ni], al[mi], bh2[ni][0], bh2[ni][1]);
                }
        }
        __syncthreads();
    }

#pragma unroll
    for (int mi = 0; mi < 2; mi++)
#pragma unroll
        for (int ni = 0; ni < 4; ni++) {
            int r = wm + mi * 16 + rr, c = wn + ni * 8 + cc;
            *(float2*)(sst + (size_t)r * SPITCH + c)       = make_float2(d[mi][ni][0], d[mi][ni][1]);
            *(float2*)(sst + (size_t)(r + 8) * SPITCH + c) = make_float2(d[mi][ni][2], d[mi][ni][3]);
        }
    __syncthreads();

    if (tid < MT && MODE == 2) {
        float4* row4 = (float4*)(sst + (size_t)tid * SPITCH);
        const float4* bv = (const float4*)s_v0;
#pragma unroll
        for (int q = 0; q < 32; q++) {
            float4 v = row4[q], b = bv[q];
            v.x = fmaxf(v.x + b.x, 0.f); v.y = fmaxf(v.y + b.y, 0.f);
            v.z = fmaxf(v.z + b.z, 0.f); v.w = fmaxf(v.w + b.w, 0.f);
            row4[q] = v;
        }
    }
    __syncthreads();

    for (int idx = tid; idx < MT * 32; idx += 256) {
        int rr2 = idx >> 5, q = idx & 31;
        float4 v = *(const float4*)(sst + (size_t)rr2 * SPITCH + q * 4);
        *(float4*)(outbase + (size_t)(n0 + rr2) * LDOUT + coff + q * 4) = v;
    }
}

// ---------------- split-K reduce + residual (+bias) + LayerNorm ----------------
// RES_EXT / OUT_EXT select harness pointers vs device globals referenced
// directly in device code. NEVER pass __device__ globals as kernel args from
// host (host shadow address + GB300 ATS = silent writes to host memory).
template <int NP, bool BIAS, bool RES_EXT, bool OUT_EXT>
__global__ void __launch_bounds__(256) ln_reduce(
    const float* __restrict__ res, const float* __restrict__ bias,
    const float* __restrict__ gam, const float* __restrict__ bet,
    float* __restrict__ outp)
{
    const int row = blockIdx.x * 8 + (threadIdx.x >> 5);
    const int lane = threadIdx.x & 31;
    const float* resp = RES_EXT ? (res + (size_t)row * 128) : (g_t + (size_t)row * 128);
    float* outrow = OUT_EXT ? (outp + (size_t)row * 128 + lane * 4)
                            : (g_t + (size_t)row * 128 + lane * 4);

    float4 acc = *(const float4*)(resp + lane * 4);
#pragma unroll
    for (int p = 0; p < NP; p++) {
        float4 v = *(const float4*)(g_part + (size_t)p * BN * DD + (size_t)row * 128 + lane * 4);
        acc.x += v.x; acc.y += v.y; acc.z += v.z; acc.w += v.w;
    }
    if (BIAS) {
        float4 b = *(const float4*)(bias + lane * 4);
        acc.x += b.x; acc.y += b.y; acc.z += b.z; acc.w += b.w;
    }
    const float mu = warp_sum(acc.x + acc.y + acc.z + acc.w) * (1.f / 128.f);
    float x0 = acc.x - mu, x1 = acc.y - mu, x2 = acc.z - mu, x3 = acc.w - mu;
    const float var = warp_sum(x0 * x0 + x1 * x1 + x2 * x2 + x3 * x3) * (1.f / 128.f);
    const float rs = rsqrtf(var + 1e-5f);
    float4 g = *(const float4*)(gam + lane * 4);
    float4 b = *(const float4*)(bet + lane * 4);
    float4 y;
    y.x = x0 * rs * g.x + b.x; y.y = x1 * rs * g.y + b.y;
    y.z = x2 * rs * g.z + b.z; y.w = x3 * rs * g.w + b.w;
    *(float4*)outrow = y;
}

// ---------------------------------------------------------------------------
extern "C" void kernel_launch(void* const* d_in, const int* in_sizes, int n_in,
                              void* d_out, int out_size)
{
    const float* h     = (const float*)d_in[0];
    const int*   adj   = (const int*)d_in[1];
    const int*   nlist = (const int*)d_in[2];
    const float* W     = (const float*)d_in[3];
    const float* a_src = (const float*)d_in[4];
    const float* a_dst = (const float*)d_in[5];
    const float* Wo    = (const float*)d_in[6];
    const float* ln1g  = (const float*)d_in[7];
    const float* ln1b  = (const float*)d_in[8];
    const float* w1    = (const float*)d_in[9];
    const float* b1    = (const float*)d_in[10];
    const float* w2    = (const float*)d_in[11];
    const float* b2    = (const float*)d_in[12];
    const float* ln2g  = (const float*)d_in[13];
    const float* ln2b  = (const float*)d_in[14];
    float* out = (float*)d_out;

    static bool attr_done = false;
    if (!attr_done) {
        cudaFuncSetAttribute(gemm_mma<1>, cudaFuncAttributeMaxDynamicSharedMemorySize, GEMM_SMEM);
        cudaFuncSetAttribute(gemm_mma<2>, cudaFuncAttributeMaxDynamicSharedMemorySize, GEMM_SMEM);
        cudaFuncSetAttribute(gemm_mma<3>, cudaFuncAttributeMaxDynamicSharedMemorySize, GEMM_SMEM);
        attr_done = true;
    }

    kfuse<<<1032, 128>>>(W, Wo, a_src, a_dst);
    prep_weights<<<256, 256>>>(w1, w2);
    ks<<<BN / 8, 256>>>(h);
    k2_attn<<<BN / 8, 256>>>(adj, nlist, h);
    gemm_mma<1><<<dim3(128, 4), 256, GEMM_SMEM>>>(nullptr, nullptr);
    // LN1: res = h (ext), out -> g_t (internal)
    ln_reduce<4, false, true, false><<<1024, 256>>>(h, nullptr, ln1g, ln1b, nullptr);
    gemm_mma<2><<<dim3(128, 2), 256, GEMM_SMEM>>>(b1, nullptr);
    gemm_mma<3><<<dim3(128, 2), 256, GEMM_SMEM>>>(nullptr, nullptr);
    // LN2: res = g_t (internal), out -> d_out (ext)
    ln_reduce<2, true, false, true><<<1024, 256>>>(nullptr, b2, ln2g, ln2b, out);
}